// round 14
// baseline (speedup 1.0000x reference)
#include <cuda_runtime.h>
#include <cuda_bf16.h>
#include <stdint.h>

// ---------------- problem constants ----------------
#define Bn 4
#define Tn 4096
#define Dn 2048
#define Hn 256
#define Wn 4
#define Mn (Bn * Tn)        // 16384
#define N2 (Dn * Wn)        // 8192

// Packed hi/lo smem-image intermediates. Image per (block, k-chunk):
// [hi 4096 elems][lo 4096 elems] = 16KB.
__device__ __nv_bfloat16 g_xpack[(size_t)(Mn / 128) * (Dn / 32) * 8192];  // 128MB
__device__ __nv_bfloat16 g_w1p[(size_t)(Hn / 128) * (Dn / 32) * 8192];    // 2MB
__device__ __nv_bfloat16 g_hpack[(size_t)(Mn / 128) * (Hn / 32) * 8192];  // 16.8MB
__device__ __nv_bfloat16 g_w2p[(size_t)(N2 / 128) * (Hn / 32) * 8192];    // 8MB

// Global barrier state (reset by last CTA each call -> graph-replay safe).
__device__ unsigned g_barIn = 0;
__device__ unsigned g_barOut = 0;

__device__ __forceinline__ float silu_f(float v) { return v / (1.0f + __expf(-v)); }

__device__ __forceinline__ uint32_t s2u(const void* p) {
    return (uint32_t)__cvta_generic_to_shared(p);
}

__device__ __forceinline__ void cp_async16(uint32_t saddr, const void* gaddr) {
    asm volatile("cp.async.cg.shared.global [%0], [%1], 16;" :: "r"(saddr), "l"(gaddr));
}
#define CP_COMMIT()  asm volatile("cp.async.commit_group;" ::: "memory")
#define CP_WAIT(N)   asm volatile("cp.async.wait_group %0;" :: "n"(N) : "memory")

__device__ __forceinline__ void mma_bf16(float* d, const uint32_t* a,
                                         uint32_t b0, uint32_t b1) {
    asm volatile(
        "mma.sync.aligned.m16n8k16.row.col.f32.bf16.bf16.f32 "
        "{%0,%1,%2,%3}, {%4,%5,%6,%7}, {%8,%9}, {%0,%1,%2,%3};"
        : "+f"(d[0]), "+f"(d[1]), "+f"(d[2]), "+f"(d[3])
        : "r"(a[0]), "r"(a[1]), "r"(a[2]), "r"(a[3]), "r"(b0), "r"(b1));
}

__device__ __forceinline__ void split_pair(float a, float b, uint32_t& hi, uint32_t& lo) {
    __nv_bfloat16 ha = __float2bfloat16_rn(a), hb = __float2bfloat16_rn(b);
    __nv_bfloat162 hw(ha, hb);
    __nv_bfloat162 lw(__float2bfloat16_rn(a - __bfloat162float(ha)),
                      __float2bfloat16_rn(b - __bfloat162float(hb)));
    hi = *(uint32_t*)&hw;
    lo = *(uint32_t*)&lw;
}

// ---------------- packed smem layout (same as R8-R13) ----------------
#define KC 32
#define SBLK 2048
#define SEC_E (2 * SBLK)               // 4096
#define CHUNK_E (4 * SEC_E)            // 16384 elems = 32KB (gemm1 stage)
#define PIPE 3
#define G1_SMEM (PIPE * CHUNK_E * 2)   // 98304

// gemm2 stage: 3 images (A0, A1, B) x 8192 elems = 48KB
#define IMG_E 8192
#define STAGE_E (3 * IMG_E)
#define G2_SMEM (PIPE * STAGE_E * 2)   // 147456

__device__ __forceinline__ void sts_pairs(__nv_bfloat16* sec, int row, int h,
                                          const uint32_t* w) {
    __nv_bfloat16* p = sec + h * SBLK + row * 16;
    #pragma unroll
    for (int j = 0; j < 4; j++) {
        uint2 u; u.x = w[j]; u.y = w[j + 4];
        *(uint2*)(p + j * 4) = u;
    }
}

// ---------------- fragment compute, 128M variant (verbatim R8-R13) ----------
__device__ __forceinline__ void compute_sub(const __nv_bfloat16* __restrict__ sbuf, int s,
                                            int lane, int wm, int wn, float acc[2][8][4]) {
    const int gid = lane >> 2, tig = lane & 3;
    const __nv_bfloat16* sA  = sbuf + s * SBLK;
    const __nv_bfloat16* sAl = sA + SEC_E;
    const __nv_bfloat16* sB  = sbuf + 2 * SEC_E + s * SBLK;
    const __nv_bfloat16* sBl = sB + SEC_E;
    const int qo = tig * 4;

    uint32_t ah[2][4], al[2][4];
    #pragma unroll
    for (int mt = 0; mt < 2; mt++) {
        const int r = wm * 32 + mt * 16 + gid;
        uint2 x0 = *(const uint2*)(sA + r * 16 + qo);
        uint2 x1 = *(const uint2*)(sA + (r + 8) * 16 + qo);
        ah[mt][0] = x0.x; ah[mt][1] = x1.x; ah[mt][2] = x0.y; ah[mt][3] = x1.y;
        uint2 y0 = *(const uint2*)(sAl + r * 16 + qo);
        uint2 y1 = *(const uint2*)(sAl + (r + 8) * 16 + qo);
        al[mt][0] = y0.x; al[mt][1] = y1.x; al[mt][2] = y0.y; al[mt][3] = y1.y;
    }

    #pragma unroll
    for (int nt = 0; nt < 8; nt++) {
        const int n = wn * 64 + nt * 8 + gid;
        uint2 bh = *(const uint2*)(sB + n * 16 + qo);
        uint2 bl = *(const uint2*)(sBl + n * 16 + qo);
        #pragma unroll
        for (int mt = 0; mt < 2; mt++) {
            float* d = acc[mt][nt];
            mma_bf16(d, ah[mt], bh.x, bh.y);
            mma_bf16(d, ah[mt], bl.x, bl.y);
            mma_bf16(d, al[mt], bh.x, bh.y);
        }
    }
}

// ---------------- fragment compute, 256M variant (B shared across m-halves) --
__device__ __forceinline__ void compute_chunk2(
    const __nv_bfloat16* __restrict__ sA0img, const __nv_bfloat16* __restrict__ sA1img,
    const __nv_bfloat16* __restrict__ sBimg, int s,
    int lane, int wm, int wn, float acc[2][2][8][4])
{
    const int gid = lane >> 2, tig = lane & 3;
    const int qo = tig * 4;

    uint32_t ah[2][2][4], al[2][2][4];   // [mhalf][mt][4]
    #pragma unroll
    for (int mh = 0; mh < 2; mh++) {
        const __nv_bfloat16* sA  = (mh ? sA1img : sA0img) + s * SBLK;
        const __nv_bfloat16* sAl = sA + SEC_E;
        #pragma unroll
        for (int mt = 0; mt < 2; mt++) {
            const int r = wm * 32 + mt * 16 + gid;
            uint2 x0 = *(const uint2*)(sA + r * 16 + qo);
            uint2 x1 = *(const uint2*)(sA + (r + 8) * 16 + qo);
            ah[mh][mt][0] = x0.x; ah[mh][mt][1] = x1.x;
            ah[mh][mt][2] = x0.y; ah[mh][mt][3] = x1.y;
            uint2 y0 = *(const uint2*)(sAl + r * 16 + qo);
            uint2 y1 = *(const uint2*)(sAl + (r + 8) * 16 + qo);
            al[mh][mt][0] = y0.x; al[mh][mt][1] = y1.x;
            al[mh][mt][2] = y0.y; al[mh][mt][3] = y1.y;
        }
    }

    const __nv_bfloat16* sB  = sBimg + s * SBLK;
    const __nv_bfloat16* sBl = sB + SEC_E;
    #pragma unroll
    for (int nt = 0; nt < 8; nt++) {
        const int n = wn * 64 + nt * 8 + gid;
        uint2 bh = *(const uint2*)(sB + n * 16 + qo);
        uint2 bl = *(const uint2*)(sBl + n * 16 + qo);
        #pragma unroll
        for (int mh = 0; mh < 2; mh++)
            #pragma unroll
            for (int mt = 0; mt < 2; mt++) {
                float* d = acc[mh][mt][nt];
                mma_bf16(d, ah[mh][mt], bh.x, bh.y);
                mma_bf16(d, ah[mh][mt], bl.x, bl.y);
                mma_bf16(d, al[mh][mt], bh.x, bh.y);
            }
    }
}

// ---------------- GEMM1 (VERBATIM R13): pack + barrier + async mainloop ------
#define NCT 256

__global__ __launch_bounds__(256, 2) void gemm1_mma_kernel(
    const float* __restrict__ X, const float* __restrict__ W1,
    const float* __restrict__ W2)
{
    extern __shared__ __align__(16) __nv_bfloat16 sm[];
    const int tid = threadIdx.x, lane = tid & 31, wid = tid >> 5;
    const int wm = wid & 3, wn = wid >> 2;
    const int nb = blockIdx.x, mb = blockIdx.y;
    const int m0 = mb * 128, n0 = nb * 128;
    const uint32_t sbase = s2u(sm);

    // ===== Phase A: cooperative packing =====
    {
        const int row = tid >> 1, khalf = tid & 1;
        for (int cc = nb * 32; cc < nb * 32 + 32; cc++) {
            const float* ap = X + (size_t)(m0 + row) * Dn + cc * KC + khalf * 16;
            float4 va0 = *(const float4*)(ap);
            float4 va1 = *(const float4*)(ap + 4);
            float4 va2 = *(const float4*)(ap + 8);
            float4 va3 = *(const float4*)(ap + 12);
            uint32_t whi[8], wlo[8];
            split_pair(va0.x, va0.y, whi[0], wlo[0]);
            split_pair(va0.z, va0.w, whi[1], wlo[1]);
            split_pair(va1.x, va1.y, whi[2], wlo[2]);
            split_pair(va1.z, va1.w, whi[3], wlo[3]);
            split_pair(va2.x, va2.y, whi[4], wlo[4]);
            split_pair(va2.z, va2.w, whi[5], wlo[5]);
            split_pair(va3.x, va3.y, whi[6], wlo[6]);
            split_pair(va3.z, va3.w, whi[7], wlo[7]);
            __nv_bfloat16* base = g_xpack + (size_t)(mb * (Dn / KC) + cc) * 8192;
            sts_pairs(base,        row, khalf, whi);
            sts_pairs(base + SEC_E, row, khalf, wlo);
        }
    }
    {
        const int gtid = (mb * 2 + nb) * 256 + tid;
        #pragma unroll
        for (int it = 0; it < 4; it++) {
            const int pid = gtid + it * 65536;
            const int n = pid & (Hn - 1);
            const int k = (pid >> 8) * 2;
            uint32_t hi, lo;
            split_pair(W1[(size_t)k * Hn + n], W1[(size_t)(k + 1) * Hn + n], hi, lo);
            const int nbk = n >> 7, nloc = n & 127;
            const int c = k >> 5, s = (k >> 4) & 1, t = (k >> 1) & 7;
            const size_t base = (size_t)(nbk * (Dn / KC) + c) * 8192
                              + s * SBLK + nloc * 16 + (t & 3) * 4 + (t >> 2) * 2;
            *(uint32_t*)(g_w1p + base)        = hi;
            *(uint32_t*)(g_w1p + base + 4096) = lo;
        }
    }
    {
        const int gtid = (mb * 2 + nb) * 256 + tid;
        #pragma unroll
        for (int it = 0; it < 16; it++) {
            const int pid = gtid + it * 65536;
            const int n = pid & (N2 - 1);
            const int k = (pid >> 13) * 2;
            uint32_t hi, lo;
            split_pair(W2[(size_t)k * N2 + n], W2[(size_t)(k + 1) * N2 + n], hi, lo);
            const int nbk = n >> 7, nloc = n & 127;
            const int c = k >> 5, s = (k >> 4) & 1, t = (k >> 1) & 7;
            const size_t base = (size_t)(nbk * (Hn / KC) + c) * 8192
                              + s * SBLK + nloc * 16 + (t & 3) * 4 + (t >> 2) * 2;
            *(uint32_t*)(g_w2p + base)        = hi;
            *(uint32_t*)(g_w2p + base + 4096) = lo;
        }
    }

    // ===== Global barrier =====
    __syncthreads();
    if (tid == 0) {
        __threadfence();
        atomicAdd(&g_barIn, 1u);
        while (*(volatile unsigned*)&g_barIn < NCT) { }
        __threadfence();
        unsigned d = atomicAdd(&g_barOut, 1u) + 1;
        if (d == NCT) {
            *(volatile unsigned*)&g_barIn = 0;
            __threadfence();
            *(volatile unsigned*)&g_barOut = 0;
        }
    }
    __syncthreads();

    // ===== Phase B: cp.async pipelined mainloop =====
    float acc[2][8][4] = {};
    const int CH = Dn / KC;

    #define G1_COPY(c) {                                                         \
        const __nv_bfloat16* ap = g_xpack + (size_t)(mb * CH + (c)) * 8192;      \
        const __nv_bfloat16* bp = g_w1p   + (size_t)(nb * CH + (c)) * 8192;      \
        const uint32_t db = sbase + ((c) % PIPE) * (CHUNK_E * 2);                \
        _Pragma("unroll")                                                        \
        for (int j = 0; j < 4; j++)                                              \
            cp_async16(db + (tid + j * 256) * 16, ap + (tid + j * 256) * 8);     \
        _Pragma("unroll")                                                        \
        for (int j = 0; j < 4; j++)                                              \
            cp_async16(db + 2 * SEC_E * 2 + (tid + j * 256) * 16,                \
                       bp + (tid + j * 256) * 8);                                \
        CP_COMMIT();                                                             \
    }

    G1_COPY(0);
    G1_COPY(1);
    for (int c = 0; c < CH; c++) {
        if (c < CH - 1) { CP_WAIT(1); } else { CP_WAIT(0); }
        __syncthreads();
        if (c + 2 < CH) G1_COPY(c + 2);
        const __nv_bfloat16* buf = sm + (c % PIPE) * CHUNK_E;
        compute_sub(buf, 0, lane, wm, wn, acc);
        compute_sub(buf, 1, lane, wm, wn, acc);
    }

    #pragma unroll
    for (int mt = 0; mt < 2; mt++) {
        const int r1 = wm * 32 + mt * 16 + (lane >> 2);
        #pragma unroll
        for (int nt = 0; nt < 8; nt++) {
            const int kcol = n0 + wn * 64 + nt * 8 + (lane & 3) * 2;
            const int cc = kcol >> 5, ss = (kcol >> 4) & 1, tt = (kcol >> 1) & 7;
            const size_t go = (size_t)(mb * (Hn / KC) + cc) * 8192
                            + ss * SBLK + (tt & 3) * 4 + (tt >> 2) * 2;
            float f0 = silu_f(acc[mt][nt][0]);
            float f1 = silu_f(acc[mt][nt][1]);
            float f2 = silu_f(acc[mt][nt][2]);
            float f3 = silu_f(acc[mt][nt][3]);
            uint32_t h01, l01, h23, l23;
            split_pair(f0, f1, h01, l01);
            split_pair(f2, f3, h23, l23);
            *(uint32_t*)(g_hpack + go + r1 * 16)              = h01;
            *(uint32_t*)(g_hpack + go + r1 * 16 + 4096)       = l01;
            *(uint32_t*)(g_hpack + go + (r1 + 8) * 16)        = h23;
            *(uint32_t*)(g_hpack + go + (r1 + 8) * 16 + 4096) = l23;
        }
    }
}

// ---------------- GEMM2: 256M x 128N tile; fused conv + silu ----------------
#define XSP 36

__global__ __launch_bounds__(256, 1) void gemm2_mma_kernel(
    const float* __restrict__ X, const float* __restrict__ B2,
    float* __restrict__ OUT)
{
    extern __shared__ __align__(16) __nv_bfloat16 sm[];
    const int tid = threadIdx.x, lane = tid & 31, wid = tid >> 5;
    const int wm = wid & 3, wn = wid >> 2;
    const int m0 = blockIdx.y * 256, n0 = blockIdx.x * 128;
    const int nb = blockIdx.x, mb = blockIdx.y;
    const uint32_t sbase = s2u(sm);
    const int CH = Hn / KC;   // 8

    float acc[2][2][8][4] = {};

    #define G2_COPY(c) {                                                         \
        const __nv_bfloat16* a0p = g_hpack + (size_t)((2 * mb) * CH + (c)) * IMG_E;     \
        const __nv_bfloat16* a1p = g_hpack + (size_t)((2 * mb + 1) * CH + (c)) * IMG_E; \
        const __nv_bfloat16* bp  = g_w2p   + (size_t)(nb * CH + (c)) * IMG_E;    \
        const uint32_t db = sbase + ((c) % PIPE) * (STAGE_E * 2);                \
        _Pragma("unroll")                                                        \
        for (int j = 0; j < 4; j++)                                              \
            cp_async16(db + (tid + j * 256) * 16, a0p + (tid + j * 256) * 8);    \
        _Pragma("unroll")                                                        \
        for (int j = 0; j < 4; j++)                                              \
            cp_async16(db + IMG_E * 2 + (tid + j * 256) * 16,                    \
                       a1p + (tid + j * 256) * 8);                               \
        _Pragma("unroll")                                                        \
        for (int j = 0; j < 4; j++)                                              \
            cp_async16(db + 2 * IMG_E * 2 + (tid + j * 256) * 16,                \
                       bp + (tid + j * 256) * 8);                                \
        CP_COMMIT();                                                             \
    }

    G2_COPY(0);
    G2_COPY(1);

    #pragma unroll
    for (int c = 0; c < CH; c++) {
        if (c < CH - 1) { CP_WAIT(1); } else { CP_WAIT(0); }
        __syncthreads();
        if (c + 2 < CH) G2_COPY(c + 2);
        const __nv_bfloat16* buf = sm + (c % PIPE) * STAGE_E;
        compute_chunk2(buf, buf + IMG_E, buf + 2 * IMG_E, 0, lane, wm, wn, acc);
        compute_chunk2(buf, buf + IMG_E, buf + 2 * IMG_E, 1, lane, wm, wn, acc);
    }
    __syncthreads();   // smem about to be reused by epilogue tiles

    // ---- Epilogue: smem-staged X window (259 rows) / bias / OUT tile ----
    float* fs = (float*)sm;
    float* xs = fs;                    // [259][XSP]
    float* os = fs + 259 * XSP;        // [256][XSP]
    float* bs = os + 256 * XSP;        // [128]
    const int d0 = n0 >> 2;
    const int brow = (m0 / Tn) * Tn;   // 256 | 4096: CTA never spans a batch

    for (int i = tid; i < 259 * 8; i += 256) {
        const int rw = i >> 3, c4 = (i & 7) * 4;
        const int gr = m0 - 3 + rw;
        float4 v = make_float4(0.f, 0.f, 0.f, 0.f);
        if (gr >= brow) v = *(const float4*)(X + (size_t)gr * Dn + d0 + c4);
        *(float4*)(xs + rw * XSP + c4) = v;
    }
    if (tid < 128) bs[tid] = B2[n0 + tid];
    __syncthreads();

    const int q = lane & 3;
    #pragma unroll
    for (int mh = 0; mh < 2; mh++) {
        #pragma unroll
        for (int mt = 0; mt < 2; mt++) {
            const int rb = mh * 128 + wm * 32 + mt * 16 + (lane >> 2);
            #pragma unroll
            for (int nt = 0; nt < 8; nt++) {
                const int colb = wn * 64 + nt * 8;
                const int col0 = colb + q * 2;
                const float bb0 = bs[col0], bb1 = bs[col0 + 1];
                float c0 = acc[mh][mt][nt][0] + bb0;
                float c1 = acc[mh][mt][nt][1] + bb1;
                float c2 = acc[mh][mt][nt][2] + bb0;
                float c3 = acc[mh][mt][nt][3] + bb1;
                float o0 = __shfl_xor_sync(0xffffffffu, c0, 1);
                float o1 = __shfl_xor_sync(0xffffffffu, c1, 1);
                float o2 = __shfl_xor_sync(0xffffffffu, c2, 1);
                float o3 = __shfl_xor_sync(0xffffffffu, c3, 1);

                float k0, k1, k2, k3;
                int rloc;
                if ((q & 1) == 0) { rloc = rb;     k0 = c0; k1 = c1; k2 = o0; k3 = o1; }
                else              { rloc = rb + 8; k0 = o2; k1 = o3; k2 = c2; k3 = c3; }
                const int dloc = (colb >> 2) + (q >> 1);

                const float* xp = xs + rloc * XSP + dloc;
                float o = k0 * xp[0] + k1 * xp[XSP] + k2 * xp[2 * XSP] + k3 * xp[3 * XSP];
                os[rloc * XSP + dloc] = silu_f(o);
            }
        }
    }
    __syncthreads();

    for (int i = tid; i < 256 * 8; i += 256) {
        const int rw = i >> 3, c4 = (i & 7) * 4;
        *(float4*)(OUT + (size_t)(m0 + rw) * Dn + d0 + c4) = *(float4*)(os + rw * XSP + c4);
    }
}

// ---------------- launch ----------------
extern "C" void kernel_launch(void* const* d_in, const int* in_sizes, int n_in,
                              void* d_out, int out_size) {
    const float* x  = (const float*)d_in[0];   // [4,4096,2048]
    const float* w1 = (const float*)d_in[1];   // [2048,256]
    const float* w2 = (const float*)d_in[2];   // [256,8192]
    const float* b2 = (const float*)d_in[3];   // [8192]
    float* out = (float*)d_out;

    cudaFuncSetAttribute(gemm1_mma_kernel,
                         cudaFuncAttributeMaxDynamicSharedMemorySize, G1_SMEM);
    cudaFuncSetAttribute(gemm2_mma_kernel,
                         cudaFuncAttributeMaxDynamicSharedMemorySize, G2_SMEM);

    gemm1_mma_kernel<<<dim3(Hn / 128, Mn / 128), 256, G1_SMEM>>>(x, w1, w2);
    gemm2_mma_kernel<<<dim3(N2 / 128, Mn / 256), 256, G2_SMEM>>>(x, b2, out);
}

// round 15
// speedup vs baseline: 1.6836x; 1.6836x over previous
#include <cuda_runtime.h>
#include <cuda_bf16.h>
#include <stdint.h>

// ---------------- problem constants ----------------
#define Bn 4
#define Tn 4096
#define Dn 2048
#define Hn 256
#define Wn 4
#define Mn (Bn * Tn)        // 16384
#define N2 (Dn * Wn)        // 8192

// Packed hi/lo smem-image intermediates. Image per (block, k-chunk):
// [hi 4096 elems][lo 4096 elems] = 16KB.
__device__ __nv_bfloat16 g_xpack[(size_t)(Mn / 128) * (Dn / 32) * 8192];
__device__ __nv_bfloat16 g_w1p[(size_t)(Hn / 128) * (Dn / 32) * 8192];
__device__ __nv_bfloat16 g_hpack[(size_t)(Mn / 128) * (Hn / 32) * 8192];
__device__ __nv_bfloat16 g_w2p[(size_t)(N2 / 128) * (Hn / 32) * 8192];

// Global barrier state (reset by last CTA each call -> graph-replay safe).
__device__ unsigned g_barIn = 0;
__device__ unsigned g_barOut = 0;

__device__ __forceinline__ float silu_f(float v) { return v / (1.0f + __expf(-v)); }

__device__ __forceinline__ uint32_t s2u(const void* p) {
    return (uint32_t)__cvta_generic_to_shared(p);
}

__device__ __forceinline__ void cp_async16(uint32_t saddr, const void* gaddr) {
    asm volatile("cp.async.cg.shared.global [%0], [%1], 16;" :: "r"(saddr), "l"(gaddr));
}
#define CP_COMMIT()  asm volatile("cp.async.commit_group;" ::: "memory")
#define CP_WAIT(N)   asm volatile("cp.async.wait_group %0;" :: "n"(N) : "memory")

__device__ __forceinline__ void mma_bf16(float* d, const uint32_t* a,
                                         uint32_t b0, uint32_t b1) {
    asm volatile(
        "mma.sync.aligned.m16n8k16.row.col.f32.bf16.bf16.f32 "
        "{%0,%1,%2,%3}, {%4,%5,%6,%7}, {%8,%9}, {%0,%1,%2,%3};"
        : "+f"(d[0]), "+f"(d[1]), "+f"(d[2]), "+f"(d[3])
        : "r"(a[0]), "r"(a[1]), "r"(a[2]), "r"(a[3]), "r"(b0), "r"(b1));
}

__device__ __forceinline__ void split_pair(float a, float b, uint32_t& hi, uint32_t& lo) {
    __nv_bfloat16 ha = __float2bfloat16_rn(a), hb = __float2bfloat16_rn(b);
    __nv_bfloat162 hw(ha, hb);
    __nv_bfloat162 lw(__float2bfloat16_rn(a - __bfloat162float(ha)),
                      __float2bfloat16_rn(b - __bfloat162float(hb)));
    hi = *(uint32_t*)&hw;
    lo = *(uint32_t*)&lw;
}

// ---------------- packed smem layout (same as R8-R13) ----------------
#define KC 32
#define SBLK 2048
#define SEC_E (2 * SBLK)               // 4096
#define CHUNK_E (4 * SEC_E)            // 16384 elems = 32KB
#define PIPE 3
#define GEMM_SMEM (PIPE * CHUNK_E * 2) // 98304
#define IMG_E 8192

__device__ __forceinline__ void sts_pairs(__nv_bfloat16* sec, int row, int h,
                                          const uint32_t* w) {
    __nv_bfloat16* p = sec + h * SBLK + row * 16;
    #pragma unroll
    for (int j = 0; j < 4; j++) {
        uint2 u; u.x = w[j]; u.y = w[j + 4];
        *(uint2*)(p + j * 4) = u;
    }
}

// ---------------- fragment compute (byte-identical to R8-R13) ----------------
__device__ __forceinline__ void compute_sub(const __nv_bfloat16* __restrict__ sbuf, int s,
                                            int lane, int wm, int wn, float acc[2][8][4]) {
    const int gid = lane >> 2, tig = lane & 3;
    const __nv_bfloat16* sA  = sbuf + s * SBLK;
    const __nv_bfloat16* sAl = sA + SEC_E;
    const __nv_bfloat16* sB  = sbuf + 2 * SEC_E + s * SBLK;
    const __nv_bfloat16* sBl = sB + SEC_E;
    const int qo = tig * 4;

    uint32_t ah[2][4], al[2][4];
    #pragma unroll
    for (int mt = 0; mt < 2; mt++) {
        const int r = wm * 32 + mt * 16 + gid;
        uint2 x0 = *(const uint2*)(sA + r * 16 + qo);
        uint2 x1 = *(const uint2*)(sA + (r + 8) * 16 + qo);
        ah[mt][0] = x0.x; ah[mt][1] = x1.x; ah[mt][2] = x0.y; ah[mt][3] = x1.y;
        uint2 y0 = *(const uint2*)(sAl + r * 16 + qo);
        uint2 y1 = *(const uint2*)(sAl + (r + 8) * 16 + qo);
        al[mt][0] = y0.x; al[mt][1] = y1.x; al[mt][2] = y0.y; al[mt][3] = y1.y;
    }

    #pragma unroll
    for (int nt = 0; nt < 8; nt++) {
        const int n = wn * 64 + nt * 8 + gid;
        uint2 bh = *(const uint2*)(sB + n * 16 + qo);
        uint2 bl = *(const uint2*)(sBl + n * 16 + qo);
        #pragma unroll
        for (int mt = 0; mt < 2; mt++) {
            float* d = acc[mt][nt];
            mma_bf16(d, ah[mt], bh.x, bh.y);
            mma_bf16(d, ah[mt], bl.x, bl.y);
            mma_bf16(d, al[mt], bh.x, bh.y);
        }
    }
}

// ---------------- GEMM1: pack(X,W1,W2) + barrier + async mainloop -------------
#define NCT 256

__global__ __launch_bounds__(256, 2) void gemm1_mma_kernel(
    const float* __restrict__ X, const float* __restrict__ W1,
    const float* __restrict__ W2)
{
    extern __shared__ __align__(16) __nv_bfloat16 sm[];
    const int tid = threadIdx.x, lane = tid & 31, wid = tid >> 5;
    const int wm = wid & 3, wn = wid >> 2;
    const int nb = blockIdx.x, mb = blockIdx.y;
    const int m0 = mb * 128, n0 = nb * 128;
    const uint32_t sbase = s2u(sm);

    // ===== Phase A: cooperative packing (verbatim R13) =====
    {
        const int row = tid >> 1, khalf = tid & 1;
        for (int cc = nb * 32; cc < nb * 32 + 32; cc++) {
            const float* ap = X + (size_t)(m0 + row) * Dn + cc * KC + khalf * 16;
            float4 va0 = *(const float4*)(ap);
            float4 va1 = *(const float4*)(ap + 4);
            float4 va2 = *(const float4*)(ap + 8);
            float4 va3 = *(const float4*)(ap + 12);
            uint32_t whi[8], wlo[8];
            split_pair(va0.x, va0.y, whi[0], wlo[0]);
            split_pair(va0.z, va0.w, whi[1], wlo[1]);
            split_pair(va1.x, va1.y, whi[2], wlo[2]);
            split_pair(va1.z, va1.w, whi[3], wlo[3]);
            split_pair(va2.x, va2.y, whi[4], wlo[4]);
            split_pair(va2.z, va2.w, whi[5], wlo[5]);
            split_pair(va3.x, va3.y, whi[6], wlo[6]);
            split_pair(va3.z, va3.w, whi[7], wlo[7]);
            __nv_bfloat16* base = g_xpack + (size_t)(mb * (Dn / KC) + cc) * IMG_E;
            sts_pairs(base,        row, khalf, whi);
            sts_pairs(base + SEC_E, row, khalf, wlo);
        }
    }
    {
        const int gtid = (mb * 2 + nb) * 256 + tid;
        #pragma unroll
        for (int it = 0; it < 4; it++) {
            const int pid = gtid + it * 65536;
            const int n = pid & (Hn - 1);
            const int k = (pid >> 8) * 2;
            uint32_t hi, lo;
            split_pair(W1[(size_t)k * Hn + n], W1[(size_t)(k + 1) * Hn + n], hi, lo);
            const int nbk = n >> 7, nloc = n & 127;
            const int c = k >> 5, s = (k >> 4) & 1, t = (k >> 1) & 7;
            const size_t base = (size_t)(nbk * (Dn / KC) + c) * IMG_E
                              + s * SBLK + nloc * 16 + (t & 3) * 4 + (t >> 2) * 2;
            *(uint32_t*)(g_w1p + base)        = hi;
            *(uint32_t*)(g_w1p + base + 4096) = lo;
        }
    }
    {
        const int gtid = (mb * 2 + nb) * 256 + tid;
        #pragma unroll
        for (int it = 0; it < 16; it++) {
            const int pid = gtid + it * 65536;
            const int n = pid & (N2 - 1);
            const int k = (pid >> 13) * 2;
            uint32_t hi, lo;
            split_pair(W2[(size_t)k * N2 + n], W2[(size_t)(k + 1) * N2 + n], hi, lo);
            const int nbk = n >> 7, nloc = n & 127;
            const int c = k >> 5, s = (k >> 4) & 1, t = (k >> 1) & 7;
            const size_t base = (size_t)(nbk * (Hn / KC) + c) * IMG_E
                              + s * SBLK + nloc * 16 + (t & 3) * 4 + (t >> 2) * 2;
            *(uint32_t*)(g_w2p + base)        = hi;
            *(uint32_t*)(g_w2p + base + 4096) = lo;
        }
    }

    // ===== Global barrier (all 256 CTAs resident: 148 SMs x 2) =====
    __syncthreads();
    if (tid == 0) {
        __threadfence();
        atomicAdd(&g_barIn, 1u);
        while (*(volatile unsigned*)&g_barIn < NCT) { }
        __threadfence();
        unsigned d = atomicAdd(&g_barOut, 1u) + 1;
        if (d == NCT) {
            *(volatile unsigned*)&g_barIn = 0;
            __threadfence();
            *(volatile unsigned*)&g_barOut = 0;
        }
    }
    __syncthreads();

    // ===== Phase B: cp.async pipelined mainloop, rotating buffers =====
    float acc[2][8][4] = {};
    const int CH = Dn / KC;   // 64

    // Incrementing global pointers (per-thread fixed lane offset).
    const __nv_bfloat16* apg = g_xpack + (size_t)(mb * CH) * IMG_E + tid * 8;
    const __nv_bfloat16* bpg = g_w1p   + (size_t)(nb * CH) * IMG_E + tid * 8;
    const uint32_t db0 = sbase + tid * 16;
    const uint32_t db1 = db0 + 2 * SEC_E * 2;

    #define G1_COPY_BUF(bufidx) {                                                \
        const uint32_t bo = (bufidx) * (CHUNK_E * 2);                             \
        _Pragma("unroll")                                                         \
        for (int j = 0; j < 4; j++)                                               \
            cp_async16(db0 + bo + j * 4096, apg + j * 2048);                      \
        _Pragma("unroll")                                                         \
        for (int j = 0; j < 4; j++)                                               \
            cp_async16(db1 + bo + j * 4096, bpg + j * 2048);                      \
        CP_COMMIT();                                                              \
        apg += IMG_E; bpg += IMG_E;                                               \
    }

    G1_COPY_BUF(0);
    G1_COPY_BUF(1);

    int cb = 0;   // compute buffer for chunk c
    int pb = 2;   // copy target buffer for chunk c+2
    #pragma unroll 4
    for (int c = 0; c < CH; c++) {
        if (c < CH - 1) { CP_WAIT(1); } else { CP_WAIT(0); }
        __syncthreads();
        if (c + 2 < CH) G1_COPY_BUF(pb);
        const __nv_bfloat16* buf = sm + cb * CHUNK_E;
        compute_sub(buf, 0, lane, wm, wn, acc);
        compute_sub(buf, 1, lane, wm, wn, acc);
        cb = (cb == 2) ? 0 : cb + 1;
        pb = (pb == 2) ? 0 : pb + 1;
    }

    // ---- Epilogue (verbatim R13): silu -> H in packed smem-image layout ----
    #pragma unroll
    for (int mt = 0; mt < 2; mt++) {
        const int r1 = wm * 32 + mt * 16 + (lane >> 2);
        #pragma unroll
        for (int nt = 0; nt < 8; nt++) {
            const int kcol = n0 + wn * 64 + nt * 8 + (lane & 3) * 2;
            const int cc = kcol >> 5, ss = (kcol >> 4) & 1, tt = (kcol >> 1) & 7;
            const size_t go = (size_t)(mb * (Hn / KC) + cc) * IMG_E
                            + ss * SBLK + (tt & 3) * 4 + (tt >> 2) * 2;
            float f0 = silu_f(acc[mt][nt][0]);
            float f1 = silu_f(acc[mt][nt][1]);
            float f2 = silu_f(acc[mt][nt][2]);
            float f3 = silu_f(acc[mt][nt][3]);
            uint32_t h01, l01, h23, l23;
            split_pair(f0, f1, h01, l01);
            split_pair(f2, f3, h23, l23);
            *(uint32_t*)(g_hpack + go + r1 * 16)              = h01;
            *(uint32_t*)(g_hpack + go + r1 * 16 + 4096)       = l01;
            *(uint32_t*)(g_hpack + go + (r1 + 8) * 16)        = h23;
            *(uint32_t*)(g_hpack + go + (r1 + 8) * 16 + 4096) = l23;
        }
    }
}

// ---------------- GEMM2 (verbatim R13): flat = H @ W2 + b2; conv + silu ------
#define XSP 36

__global__ __launch_bounds__(256, 2) void gemm2_mma_kernel(
    const float* __restrict__ X, const float* __restrict__ B2,
    float* __restrict__ OUT)
{
    extern __shared__ __align__(16) __nv_bfloat16 sm[];
    const int tid = threadIdx.x, lane = tid & 31, wid = tid >> 5;
    const int wm = wid & 3, wn = wid >> 2;
    const int m0 = blockIdx.y * 128, n0 = blockIdx.x * 128;
    const int nb = blockIdx.x, mb = blockIdx.y;
    const uint32_t sbase = s2u(sm);
    const int CH = Hn / KC;   // 8

    float acc[2][8][4] = {};

    #define G2_COPY(c) {                                                         \
        const __nv_bfloat16* ap = g_hpack + (size_t)(mb * CH + (c)) * IMG_E;     \
        const __nv_bfloat16* bp = g_w2p  + (size_t)(nb * CH + (c)) * IMG_E;      \
        const uint32_t db = sbase + ((c) % PIPE) * (CHUNK_E * 2);                \
        _Pragma("unroll")                                                        \
        for (int j = 0; j < 4; j++)                                              \
            cp_async16(db + (tid + j * 256) * 16, ap + (tid + j * 256) * 8);     \
        _Pragma("unroll")                                                        \
        for (int j = 0; j < 4; j++)                                              \
            cp_async16(db + 2 * SEC_E * 2 + (tid + j * 256) * 16,                \
                       bp + (tid + j * 256) * 8);                                \
        CP_COMMIT();                                                             \
    }

    G2_COPY(0);
    G2_COPY(1);

    #pragma unroll
    for (int c = 0; c < CH; c++) {
        if (c < CH - 1) { CP_WAIT(1); } else { CP_WAIT(0); }
        __syncthreads();
        if (c + 2 < CH) G2_COPY(c + 2);
        const __nv_bfloat16* buf = sm + (c % PIPE) * CHUNK_E;
        compute_sub(buf, 0, lane, wm, wn, acc);
        compute_sub(buf, 1, lane, wm, wn, acc);
    }
    __syncthreads();   // smem about to be reused by the epilogue tiles

    // ---- Epilogue (verbatim R9-R13): smem-staged X window / bias / OUT ----
    float* fs = (float*)sm;
    float* xs = fs;
    float* os = fs + 131 * XSP;
    float* bs = os + 128 * XSP;
    const int d0 = n0 >> 2;
    const int brow = (m0 / Tn) * Tn;

    for (int i = tid; i < 131 * 8; i += 256) {
        const int rw = i >> 3, c4 = (i & 7) * 4;
        const int gr = m0 - 3 + rw;
        float4 v = make_float4(0.f, 0.f, 0.f, 0.f);
        if (gr >= brow) v = *(const float4*)(X + (size_t)gr * Dn + d0 + c4);
        *(float4*)(xs + rw * XSP + c4) = v;
    }
    if (tid < 128) bs[tid] = B2[n0 + tid];
    __syncthreads();

    const int q = lane & 3;
    #pragma unroll
    for (int mt = 0; mt < 2; mt++) {
        const int rb = wm * 32 + mt * 16 + (lane >> 2);
        #pragma unroll
        for (int nt = 0; nt < 8; nt++) {
            const int colb = wn * 64 + nt * 8;
            const int col0 = colb + q * 2;
            const float bb0 = bs[col0], bb1 = bs[col0 + 1];
            float c0 = acc[mt][nt][0] + bb0;
            float c1 = acc[mt][nt][1] + bb1;
            float c2 = acc[mt][nt][2] + bb0;
            float c3 = acc[mt][nt][3] + bb1;
            float o0 = __shfl_xor_sync(0xffffffffu, c0, 1);
            float o1 = __shfl_xor_sync(0xffffffffu, c1, 1);
            float o2 = __shfl_xor_sync(0xffffffffu, c2, 1);
            float o3 = __shfl_xor_sync(0xffffffffu, c3, 1);

            float k0, k1, k2, k3;
            int rloc;
            if ((q & 1) == 0) { rloc = rb;     k0 = c0; k1 = c1; k2 = o0; k3 = o1; }
            else              { rloc = rb + 8; k0 = o2; k1 = o3; k2 = c2; k3 = c3; }
            const int dloc = (colb >> 2) + (q >> 1);

            const float* xp = xs + rloc * XSP + dloc;
            float o = k0 * xp[0] + k1 * xp[XSP] + k2 * xp[2 * XSP] + k3 * xp[3 * XSP];
            os[rloc * XSP + dloc] = silu_f(o);
        }
    }
    __syncthreads();

    for (int i = tid; i < 128 * 8; i += 256) {
        const int rw = i >> 3, c4 = (i & 7) * 4;
        *(float4*)(OUT + (size_t)(m0 + rw) * Dn + d0 + c4) = *(float4*)(os + rw * XSP + c4);
    }
}

// ---------------- launch ----------------
extern "C" void kernel_launch(void* const* d_in, const int* in_sizes, int n_in,
                              void* d_out, int out_size) {
    const float* x  = (const float*)d_in[0];   // [4,4096,2048]
    const float* w1 = (const float*)d_in[1];   // [2048,256]
    const float* w2 = (const float*)d_in[2];   // [256,8192]
    const float* b2 = (const float*)d_in[3];   // [8192]
    float* out = (float*)d_out;

    cudaFuncSetAttribute(gemm1_mma_kernel,
                         cudaFuncAttributeMaxDynamicSharedMemorySize, GEMM_SMEM);
    cudaFuncSetAttribute(gemm2_mma_kernel,
                         cudaFuncAttributeMaxDynamicSharedMemorySize, GEMM_SMEM);

    gemm1_mma_kernel<<<dim3(Hn / 128, Mn / 128), 256, GEMM_SMEM>>>(x, w1, w2);
    gemm2_mma_kernel<<<dim3(N2 / 128, Mn / 128), 256, GEMM_SMEM>>>(x, b2, out);
}

// round 16
// speedup vs baseline: 2.1858x; 1.2983x over previous
#include <cuda_runtime.h>
#include <cuda_fp16.h>
#include <stdint.h>

// ---------------- problem constants ----------------
#define Bn 4
#define Tn 4096
#define Dn 2048
#define Hn 256
#define Wn 4
#define Mn (Bn * Tn)        // 16384
#define N2 (Dn * Wn)        // 8192

// ---------------- layout constants ----------------
#define KC 32
#define SBLK 2048                       // elems per s-block (128 rows x 16)
#define SEC_E (2 * SBLK)                // 4096 elems per section
#define IMG_A 8192                      // A image: [hi 4096][lo 4096] fp16 = 16KB
#define IMG_B 4096                      // B image: [hi 4096] fp16 = 8KB
#define STG_E (3 * SEC_E)               // stage = A(2 sec) + B(1 sec) = 12288 elems
#define STG_B (STG_E * 2)               // 24576 bytes
#define PIPE 4
#define GEMM_SMEM (PIPE * STG_B)        // 98304

// Packed fp16 intermediates (written by gemm1 / in-kernel packers only).
__device__ __half g_xpack[(size_t)(Mn / 128) * (Dn / KC) * IMG_A];  // 128MB
__device__ __half g_w1p[(size_t)(Hn / 128) * (Dn / KC) * IMG_B];    // 1MB
__device__ __half g_hpack[(size_t)(Mn / 128) * (Hn / KC) * IMG_A];  // 16.8MB
__device__ __half g_w2p[(size_t)(N2 / 128) * (Hn / KC) * IMG_B];    // 4MB

// Global barrier state (reset by last CTA each call -> graph-replay safe).
__device__ unsigned g_barIn = 0;
__device__ unsigned g_barOut = 0;

__device__ __forceinline__ float silu_f(float v) { return v / (1.0f + __expf(-v)); }

__device__ __forceinline__ uint32_t s2u(const void* p) {
    return (uint32_t)__cvta_generic_to_shared(p);
}

__device__ __forceinline__ void cp_async16(uint32_t saddr, const void* gaddr) {
    asm volatile("cp.async.cg.shared.global [%0], [%1], 16;" :: "r"(saddr), "l"(gaddr));
}
#define CP_COMMIT()  asm volatile("cp.async.commit_group;" ::: "memory")
#define CP_WAIT(N)   asm volatile("cp.async.wait_group %0;" :: "n"(N) : "memory")

__device__ __forceinline__ void mma_f16(float* d, const uint32_t* a,
                                        uint32_t b0, uint32_t b1) {
    asm volatile(
        "mma.sync.aligned.m16n8k16.row.col.f32.f16.f16.f32 "
        "{%0,%1,%2,%3}, {%4,%5,%6,%7}, {%8,%9}, {%0,%1,%2,%3};"
        : "+f"(d[0]), "+f"(d[1]), "+f"(d[2]), "+f"(d[3])
        : "r"(a[0]), "r"(a[1]), "r"(a[2]), "r"(a[3]), "r"(b0), "r"(b1));
}

// A-side split: a = hi + lo (22 mantissa bits total).
__device__ __forceinline__ void split_pair(float a, float b, uint32_t& hi, uint32_t& lo) {
    __half ha = __float2half_rn(a), hb = __float2half_rn(b);
    __half2 hw(ha, hb);
    __half2 lw(__float2half_rn(a - __half2float(ha)),
               __float2half_rn(b - __half2float(hb)));
    hi = *(uint32_t*)&hw;
    lo = *(uint32_t*)&lw;
}
// B-side: single rounding.
__device__ __forceinline__ uint32_t pack_single(float a, float b) {
    __half2 w(__float2half_rn(a), __float2half_rn(b));
    return *(uint32_t*)&w;
}

__device__ __forceinline__ void sts_pairs(__half* sec, int row, int h,
                                          const uint32_t* w) {
    __half* p = sec + h * SBLK + row * 16;
    #pragma unroll
    for (int j = 0; j < 4; j++) {
        uint2 u; u.x = w[j]; u.y = w[j + 4];
        *(uint2*)(p + j * 4) = u;
    }
}

// ---------------- fragment compute: 2 MMAs per (mt, nt) ----------------
__device__ __forceinline__ void compute_sub(const __half* __restrict__ sbuf, int s,
                                            int lane, int wm, int wn, float acc[2][8][4]) {
    const int gid = lane >> 2, tig = lane & 3;
    const __half* sA  = sbuf + s * SBLK;             // A hi
    const __half* sAl = sbuf + SEC_E + s * SBLK;     // A lo
    const __half* sB  = sbuf + 2 * SEC_E + s * SBLK; // B
    const int qo = tig * 4;

    uint32_t ah[2][4], al[2][4];
    #pragma unroll
    for (int mt = 0; mt < 2; mt++) {
        const int r = wm * 32 + mt * 16 + gid;
        uint2 x0 = *(const uint2*)(sA + r * 16 + qo);
        uint2 x1 = *(const uint2*)(sA + (r + 8) * 16 + qo);
        ah[mt][0] = x0.x; ah[mt][1] = x1.x; ah[mt][2] = x0.y; ah[mt][3] = x1.y;
        uint2 y0 = *(const uint2*)(sAl + r * 16 + qo);
        uint2 y1 = *(const uint2*)(sAl + (r + 8) * 16 + qo);
        al[mt][0] = y0.x; al[mt][1] = y1.x; al[mt][2] = y0.y; al[mt][3] = y1.y;
    }

    #pragma unroll
    for (int nt = 0; nt < 8; nt++) {
        const int n = wn * 64 + nt * 8 + gid;
        uint2 bh = *(const uint2*)(sB + n * 16 + qo);
        #pragma unroll
        for (int mt = 0; mt < 2; mt++) {
            float* d = acc[mt][nt];
            mma_f16(d, ah[mt], bh.x, bh.y);
            mma_f16(d, al[mt], bh.x, bh.y);
        }
    }
}

// ---------------- GEMM1: pack(X,W1,W2) + barrier + async mainloop -------------
#define NCT 256

__global__ __launch_bounds__(256, 2) void gemm1_mma_kernel(
    const float* __restrict__ X, const float* __restrict__ W1,
    const float* __restrict__ W2)
{
    extern __shared__ __align__(16) __half sm[];
    const int tid = threadIdx.x, lane = tid & 31, wid = tid >> 5;
    const int wm = wid & 3, wn = wid >> 2;
    const int nb = blockIdx.x, mb = blockIdx.y;
    const int m0 = mb * 128, n0 = nb * 128;
    const uint32_t sbase = s2u(sm);

    // ===== Phase A: cooperative packing =====
    // X pack (A-type image, hi/lo): this CTA packs chunks [nb*32, nb*32+32).
    {
        const int row = tid >> 1, khalf = tid & 1;
        for (int cc = nb * 32; cc < nb * 32 + 32; cc++) {
            const float* ap = X + (size_t)(m0 + row) * Dn + cc * KC + khalf * 16;
            float4 va0 = *(const float4*)(ap);
            float4 va1 = *(const float4*)(ap + 4);
            float4 va2 = *(const float4*)(ap + 8);
            float4 va3 = *(const float4*)(ap + 12);
            uint32_t whi[8], wlo[8];
            split_pair(va0.x, va0.y, whi[0], wlo[0]);
            split_pair(va0.z, va0.w, whi[1], wlo[1]);
            split_pair(va1.x, va1.y, whi[2], wlo[2]);
            split_pair(va1.z, va1.w, whi[3], wlo[3]);
            split_pair(va2.x, va2.y, whi[4], wlo[4]);
            split_pair(va2.z, va2.w, whi[5], wlo[5]);
            split_pair(va3.x, va3.y, whi[6], wlo[6]);
            split_pair(va3.z, va3.w, whi[7], wlo[7]);
            __half* base = g_xpack + (size_t)(mb * (Dn / KC) + cc) * IMG_A;
            sts_pairs(base,        row, khalf, whi);
            sts_pairs(base + SEC_E, row, khalf, wlo);
        }
    }
    // W1 pack (B-type image, hi only): 4 items/thread.
    {
        const int gtid = (mb * 2 + nb) * 256 + tid;
        #pragma unroll
        for (int it = 0; it < 4; it++) {
            const int pid = gtid + it * 65536;
            const int n = pid & (Hn - 1);
            const int k = (pid >> 8) * 2;
            uint32_t hi = pack_single(W1[(size_t)k * Hn + n], W1[(size_t)(k + 1) * Hn + n]);
            const int nbk = n >> 7, nloc = n & 127;
            const int c = k >> 5, s = (k >> 4) & 1, t = (k >> 1) & 7;
            const size_t base = (size_t)(nbk * (Dn / KC) + c) * IMG_B
                              + s * SBLK + nloc * 16 + (t & 3) * 4 + (t >> 2) * 2;
            *(uint32_t*)(g_w1p + base) = hi;
        }
    }
    // W2 pack (B-type image, hi only): 16 items/thread.
    {
        const int gtid = (mb * 2 + nb) * 256 + tid;
        #pragma unroll
        for (int it = 0; it < 16; it++) {
            const int pid = gtid + it * 65536;
            const int n = pid & (N2 - 1);
            const int k = (pid >> 13) * 2;
            uint32_t hi = pack_single(W2[(size_t)k * N2 + n], W2[(size_t)(k + 1) * N2 + n]);
            const int nbk = n >> 7, nloc = n & 127;
            const int c = k >> 5, s = (k >> 4) & 1, t = (k >> 1) & 7;
            const size_t base = (size_t)(nbk * (Hn / KC) + c) * IMG_B
                              + s * SBLK + nloc * 16 + (t & 3) * 4 + (t >> 2) * 2;
            *(uint32_t*)(g_w2p + base) = hi;
        }
    }

    // ===== Global barrier (all 256 CTAs resident: 148 SMs x 2) =====
    __syncthreads();
    if (tid == 0) {
        __threadfence();
        atomicAdd(&g_barIn, 1u);
        while (*(volatile unsigned*)&g_barIn < NCT) { }
        __threadfence();
        unsigned d = atomicAdd(&g_barOut, 1u) + 1;
        if (d == NCT) {
            *(volatile unsigned*)&g_barIn = 0;
            __threadfence();
            *(volatile unsigned*)&g_barOut = 0;
        }
    }
    __syncthreads();

    // ===== Phase B: cp.async pipelined mainloop (PIPE = 4) =====
    float acc[2][8][4] = {};
    const int CH = Dn / KC;   // 64

    const __half* apg = g_xpack + (size_t)(mb * CH) * IMG_A + tid * 8;
    const __half* bpg = g_w1p   + (size_t)(nb * CH) * IMG_B + tid * 8;
    const uint32_t db0 = sbase + tid * 16;
    const uint32_t db1 = db0 + 2 * SEC_E * 2;

    #define G1_COPY_BUF(bufidx) {                                                 \
        const uint32_t bo = (bufidx) * STG_B;                                      \
        _Pragma("unroll")                                                          \
        for (int j = 0; j < 4; j++)                                                \
            cp_async16(db0 + bo + j * 4096, apg + j * 2048);                       \
        _Pragma("unroll")                                                          \
        for (int j = 0; j < 2; j++)                                                \
            cp_async16(db1 + bo + j * 4096, bpg + j * 2048);                       \
        CP_COMMIT();                                                               \
        apg += IMG_A; bpg += IMG_B;                                                \
    }

    G1_COPY_BUF(0);
    G1_COPY_BUF(1);
    G1_COPY_BUF(2);

    int cb = 0;   // compute buffer for chunk c
    int pb = 3;   // copy target buffer for chunk c+3
    #pragma unroll 4
    for (int c = 0; c < CH; c++) {
        if (c < CH - 1) { CP_WAIT(2); } else { CP_WAIT(0); }
        __syncthreads();
        if (c + 3 < CH) G1_COPY_BUF(pb);
        const __half* buf = sm + cb * STG_E;
        compute_sub(buf, 0, lane, wm, wn, acc);
        compute_sub(buf, 1, lane, wm, wn, acc);
        cb = (cb + 1) & 3;
        pb = (pb + 1) & 3;
    }

    // ---- Epilogue: silu -> H in packed A-type image (hi/lo fp16) ----
    #pragma unroll
    for (int mt = 0; mt < 2; mt++) {
        const int r1 = wm * 32 + mt * 16 + (lane >> 2);
        #pragma unroll
        for (int nt = 0; nt < 8; nt++) {
            const int kcol = n0 + wn * 64 + nt * 8 + (lane & 3) * 2;
            const int cc = kcol >> 5, ss = (kcol >> 4) & 1, tt = (kcol >> 1) & 7;
            const size_t go = (size_t)(mb * (Hn / KC) + cc) * IMG_A
                            + ss * SBLK + (tt & 3) * 4 + (tt >> 2) * 2;
            float f0 = silu_f(acc[mt][nt][0]);
            float f1 = silu_f(acc[mt][nt][1]);
            float f2 = silu_f(acc[mt][nt][2]);
            float f3 = silu_f(acc[mt][nt][3]);
            uint32_t h01, l01, h23, l23;
            split_pair(f0, f1, h01, l01);
            split_pair(f2, f3, h23, l23);
            *(uint32_t*)(g_hpack + go + r1 * 16)              = h01;
            *(uint32_t*)(g_hpack + go + r1 * 16 + SEC_E)      = l01;
            *(uint32_t*)(g_hpack + go + (r1 + 8) * 16)         = h23;
            *(uint32_t*)(g_hpack + go + (r1 + 8) * 16 + SEC_E) = l23;
        }
    }
}

// ---------------- GEMM2: flat = H @ W2 + b2; fused conv + silu ----------------
#define XSP 36

__global__ __launch_bounds__(256, 2) void gemm2_mma_kernel(
    const float* __restrict__ X, const float* __restrict__ B2,
    float* __restrict__ OUT)
{
    extern __shared__ __align__(16) __half sm[];
    const int tid = threadIdx.x, lane = tid & 31, wid = tid >> 5;
    const int wm = wid & 3, wn = wid >> 2;
    const int m0 = blockIdx.y * 128, n0 = blockIdx.x * 128;
    const int nb = blockIdx.x, mb = blockIdx.y;
    const uint32_t sbase = s2u(sm);
    const int CH = Hn / KC;   // 8

    float acc[2][8][4] = {};

    #define G2_COPY(c) {                                                          \
        const __half* ap = g_hpack + (size_t)(mb * CH + (c)) * IMG_A;             \
        const __half* bp = g_w2p  + (size_t)(nb * CH + (c)) * IMG_B;              \
        const uint32_t db = sbase + ((c) & 3) * STG_B;                            \
        _Pragma("unroll")                                                         \
        for (int j = 0; j < 4; j++)                                               \
            cp_async16(db + (tid + j * 256) * 16, ap + (tid + j * 256) * 8);      \
        _Pragma("unroll")                                                         \
        for (int j = 0; j < 2; j++)                                               \
            cp_async16(db + 2 * SEC_E * 2 + (tid + j * 256) * 16,                 \
                       bp + (tid + j * 256) * 8);                                 \
        CP_COMMIT();                                                              \
    }

    G2_COPY(0);
    G2_COPY(1);
    G2_COPY(2);

    #pragma unroll
    for (int c = 0; c < CH; c++) {
        if (c < CH - 1) { CP_WAIT(2); } else { CP_WAIT(0); }
        __syncthreads();
        if (c + 3 < CH) G2_COPY(c + 3);
        const __half* buf = sm + (c & 3) * STG_E;
        compute_sub(buf, 0, lane, wm, wn, acc);
        compute_sub(buf, 1, lane, wm, wn, acc);
    }
    __syncthreads();   // smem about to be reused by the epilogue tiles

    // ---- Epilogue (structure verbatim R9-R15): X window / bias / OUT ----
    float* fs = (float*)sm;
    float* xs = fs;
    float* os = fs + 131 * XSP;
    float* bs = os + 128 * XSP;
    const int d0 = n0 >> 2;
    const int brow = (m0 / Tn) * Tn;

    for (int i = tid; i < 131 * 8; i += 256) {
        const int rw = i >> 3, c4 = (i & 7) * 4;
        const int gr = m0 - 3 + rw;
        float4 v = make_float4(0.f, 0.f, 0.f, 0.f);
        if (gr >= brow) v = *(const float4*)(X + (size_t)gr * Dn + d0 + c4);
        *(float4*)(xs + rw * XSP + c4) = v;
    }
    if (tid < 128) bs[tid] = B2[n0 + tid];
    __syncthreads();

    const int q = lane & 3;
    #pragma unroll
    for (int mt = 0; mt < 2; mt++) {
        const int rb = wm * 32 + mt * 16 + (lane >> 2);
        #pragma unroll
        for (int nt = 0; nt < 8; nt++) {
            const int colb = wn * 64 + nt * 8;
            const int col0 = colb + q * 2;
            const float bb0 = bs[col0], bb1 = bs[col0 + 1];
            float c0 = acc[mt][nt][0] + bb0;
            float c1 = acc[mt][nt][1] + bb1;
            float c2 = acc[mt][nt][2] + bb0;
            float c3 = acc[mt][nt][3] + bb1;
            float o0 = __shfl_xor_sync(0xffffffffu, c0, 1);
            float o1 = __shfl_xor_sync(0xffffffffu, c1, 1);
            float o2 = __shfl_xor_sync(0xffffffffu, c2, 1);
            float o3 = __shfl_xor_sync(0xffffffffu, c3, 1);

            float k0, k1, k2, k3;
            int rloc;
            if ((q & 1) == 0) { rloc = rb;     k0 = c0; k1 = c1; k2 = o0; k3 = o1; }
            else              { rloc = rb + 8; k0 = o2; k1 = o3; k2 = c2; k3 = c3; }
            const int dloc = (colb >> 2) + (q >> 1);

            const float* xp = xs + rloc * XSP + dloc;
            float o = k0 * xp[0] + k1 * xp[XSP] + k2 * xp[2 * XSP] + k3 * xp[3 * XSP];
            os[rloc * XSP + dloc] = silu_f(o);
        }
    }
    __syncthreads();

    for (int i = tid; i < 128 * 8; i += 256) {
        const int rw = i >> 3, c4 = (i & 7) * 4;
        *(float4*)(OUT + (size_t)(m0 + rw) * Dn + d0 + c4) = *(float4*)(os + rw * XSP + c4);
    }
}

// ---------------- launch ----------------
extern "C" void kernel_launch(void* const* d_in, const int* in_sizes, int n_in,
                              void* d_out, int out_size) {
    const float* x  = (const float*)d_in[0];   // [4,4096,2048]
    const float* w1 = (const float*)d_in[1];   // [2048,256]
    const float* w2 = (const float*)d_in[2];   // [256,8192]
    const float* b2 = (const float*)d_in[3];   // [8192]
    float* out = (float*)d_out;

    cudaFuncSetAttribute(gemm1_mma_kernel,
                         cudaFuncAttributeMaxDynamicSharedMemorySize, GEMM_SMEM);
    cudaFuncSetAttribute(gemm2_mma_kernel,
                         cudaFuncAttributeMaxDynamicSharedMemorySize, GEMM_SMEM);

    gemm1_mma_kernel<<<dim3(Hn / 128, Mn / 128), 256, GEMM_SMEM>>>(x, w1, w2);
    gemm2_mma_kernel<<<dim3(N2 / 128, Mn / 128), 256, GEMM_SMEM>>>(x, b2, out);
}

// round 17
// speedup vs baseline: 2.7628x; 1.2640x over previous
#include <cuda_runtime.h>
#include <cuda_fp16.h>
#include <stdint.h>

// ---------------- problem constants ----------------
#define Bn 4
#define Tn 4096
#define Dn 2048
#define Hn 256
#define Wn 4
#define Mn (Bn * Tn)        // 16384
#define N2 (Dn * Wn)        // 8192

// ---------------- layout constants ----------------
#define KC 32
#define SBLK 2048                       // elems per s-block (128 rows x 16)
#define SEC_E (2 * SBLK)                // 4096 elems per section
#define IMG_A 8192                      // gemm1 A image: [hi 4096][lo 4096] fp16
#define IMG_B 4096                      // B image: [hi 4096] fp16 = 8KB
#define IMG_H 4096                      // gemm2 A image: hi only = 8KB

// gemm1 stage: A(2 sec) + B(1 sec) = 24KB, PIPE 4
#define STG1_E (3 * SEC_E)
#define STG1_B (STG1_E * 2)
#define PIPE1 4
#define G1_SMEM (PIPE1 * STG1_B)        // 98304

// gemm2 stage: A(1 sec) + B(1 sec) = 16KB, PIPE 6
#define STG2_E (2 * SEC_E)
#define STG2_B (STG2_E * 2)
#define PIPE2 6
#define G2_SMEM (PIPE2 * STG2_B)        // 98304

// Packed fp16 intermediates (written by gemm1 / in-kernel packers only).
__device__ __half g_xpack[(size_t)(Mn / 128) * (Dn / KC) * IMG_A];  // 128MB
__device__ __half g_w1p[(size_t)(Hn / 128) * (Dn / KC) * IMG_B];    // 1MB
__device__ __half g_hpack[(size_t)(Mn / 128) * (Hn / KC) * IMG_H];  // 8.4MB
__device__ __half g_w2p[(size_t)(N2 / 128) * (Hn / KC) * IMG_B];    // 4MB

// Global barrier state (reset by last CTA each call -> graph-replay safe).
__device__ unsigned g_barIn = 0;
__device__ unsigned g_barOut = 0;

__device__ __forceinline__ float silu_f(float v) { return v / (1.0f + __expf(-v)); }

__device__ __forceinline__ uint32_t s2u(const void* p) {
    return (uint32_t)__cvta_generic_to_shared(p);
}

__device__ __forceinline__ void cp_async16(uint32_t saddr, const void* gaddr) {
    asm volatile("cp.async.cg.shared.global [%0], [%1], 16;" :: "r"(saddr), "l"(gaddr));
}
#define CP_COMMIT()  asm volatile("cp.async.commit_group;" ::: "memory")
#define CP_WAIT(N)   asm volatile("cp.async.wait_group %0;" :: "n"(N) : "memory")

__device__ __forceinline__ void mma_f16(float* d, const uint32_t* a,
                                        uint32_t b0, uint32_t b1) {
    asm volatile(
        "mma.sync.aligned.m16n8k16.row.col.f32.f16.f16.f32 "
        "{%0,%1,%2,%3}, {%4,%5,%6,%7}, {%8,%9}, {%0,%1,%2,%3};"
        : "+f"(d[0]), "+f"(d[1]), "+f"(d[2]), "+f"(d[3])
        : "r"(a[0]), "r"(a[1]), "r"(a[2]), "r"(a[3]), "r"(b0), "r"(b1));
}

// A-side split: a = hi + lo (22 mantissa bits total).
__device__ __forceinline__ void split_pair(float a, float b, uint32_t& hi, uint32_t& lo) {
    __half ha = __float2half_rn(a), hb = __float2half_rn(b);
    __half2 hw(ha, hb);
    __half2 lw(__float2half_rn(a - __half2float(ha)),
               __float2half_rn(b - __half2float(hb)));
    hi = *(uint32_t*)&hw;
    lo = *(uint32_t*)&lw;
}
__device__ __forceinline__ uint32_t pack_single(float a, float b) {
    __half2 w(__float2half_rn(a), __float2half_rn(b));
    return *(uint32_t*)&w;
}

__device__ __forceinline__ void sts_pairs(__half* sec, int row, int h,
                                          const uint32_t* w) {
    __half* p = sec + h * SBLK + row * 16;
    #pragma unroll
    for (int j = 0; j < 4; j++) {
        uint2 u; u.x = w[j]; u.y = w[j + 4];
        *(uint2*)(p + j * 4) = u;
    }
}

// ---------------- gemm1 fragment compute: A hi/lo, 2 MMAs (verbatim R16) -----
__device__ __forceinline__ void compute_sub1(const __half* __restrict__ sbuf, int s,
                                             int lane, int wm, int wn, float acc[2][8][4]) {
    const int gid = lane >> 2, tig = lane & 3;
    const __half* sA  = sbuf + s * SBLK;
    const __half* sAl = sbuf + SEC_E + s * SBLK;
    const __half* sB  = sbuf + 2 * SEC_E + s * SBLK;
    const int qo = tig * 4;

    uint32_t ah[2][4], al[2][4];
    #pragma unroll
    for (int mt = 0; mt < 2; mt++) {
        const int r = wm * 32 + mt * 16 + gid;
        uint2 x0 = *(const uint2*)(sA + r * 16 + qo);
        uint2 x1 = *(const uint2*)(sA + (r + 8) * 16 + qo);
        ah[mt][0] = x0.x; ah[mt][1] = x1.x; ah[mt][2] = x0.y; ah[mt][3] = x1.y;
        uint2 y0 = *(const uint2*)(sAl + r * 16 + qo);
        uint2 y1 = *(const uint2*)(sAl + (r + 8) * 16 + qo);
        al[mt][0] = y0.x; al[mt][1] = y1.x; al[mt][2] = y0.y; al[mt][3] = y1.y;
    }

    #pragma unroll
    for (int nt = 0; nt < 8; nt++) {
        const int n = wn * 64 + nt * 8 + gid;
        uint2 bh = *(const uint2*)(sB + n * 16 + qo);
        #pragma unroll
        for (int mt = 0; mt < 2; mt++) {
            float* d = acc[mt][nt];
            mma_f16(d, ah[mt], bh.x, bh.y);
            mma_f16(d, al[mt], bh.x, bh.y);
        }
    }
}

// ---------------- gemm2 fragment compute: A single fp16, 1 MMA ----------------
__device__ __forceinline__ void compute_sub2(const __half* __restrict__ sbuf, int s,
                                             int lane, int wm, int wn, float acc[2][8][4]) {
    const int gid = lane >> 2, tig = lane & 3;
    const __half* sA = sbuf + s * SBLK;
    const __half* sB = sbuf + SEC_E + s * SBLK;
    const int qo = tig * 4;

    uint32_t ah[2][4];
    #pragma unroll
    for (int mt = 0; mt < 2; mt++) {
        const int r = wm * 32 + mt * 16 + gid;
        uint2 x0 = *(const uint2*)(sA + r * 16 + qo);
        uint2 x1 = *(const uint2*)(sA + (r + 8) * 16 + qo);
        ah[mt][0] = x0.x; ah[mt][1] = x1.x; ah[mt][2] = x0.y; ah[mt][3] = x1.y;
    }

    #pragma unroll
    for (int nt = 0; nt < 8; nt++) {
        const int n = wn * 64 + nt * 8 + gid;
        uint2 bh = *(const uint2*)(sB + n * 16 + qo);
        #pragma unroll
        for (int mt = 0; mt < 2; mt++)
            mma_f16(acc[mt][nt], ah[mt], bh.x, bh.y);
    }
}

// ---------------- GEMM1: pack(X,W1,W2) + barrier + async mainloop -------------
#define NCT 256

__global__ __launch_bounds__(256, 2) void gemm1_mma_kernel(
    const float* __restrict__ X, const float* __restrict__ W1,
    const float* __restrict__ W2)
{
    extern __shared__ __align__(16) __half sm[];
    const int tid = threadIdx.x, lane = tid & 31, wid = tid >> 5;
    const int wm = wid & 3, wn = wid >> 2;
    const int nb = blockIdx.x, mb = blockIdx.y;
    const int m0 = mb * 128, n0 = nb * 128;
    const uint32_t sbase = s2u(sm);

    // ===== Phase A: cooperative packing (verbatim R16) =====
    {
        const int row = tid >> 1, khalf = tid & 1;
        for (int cc = nb * 32; cc < nb * 32 + 32; cc++) {
            const float* ap = X + (size_t)(m0 + row) * Dn + cc * KC + khalf * 16;
            float4 va0 = *(const float4*)(ap);
            float4 va1 = *(const float4*)(ap + 4);
            float4 va2 = *(const float4*)(ap + 8);
            float4 va3 = *(const float4*)(ap + 12);
            uint32_t whi[8], wlo[8];
            split_pair(va0.x, va0.y, whi[0], wlo[0]);
            split_pair(va0.z, va0.w, whi[1], wlo[1]);
            split_pair(va1.x, va1.y, whi[2], wlo[2]);
            split_pair(va1.z, va1.w, whi[3], wlo[3]);
            split_pair(va2.x, va2.y, whi[4], wlo[4]);
            split_pair(va2.z, va2.w, whi[5], wlo[5]);
            split_pair(va3.x, va3.y, whi[6], wlo[6]);
            split_pair(va3.z, va3.w, whi[7], wlo[7]);
            __half* base = g_xpack + (size_t)(mb * (Dn / KC) + cc) * IMG_A;
            sts_pairs(base,        row, khalf, whi);
            sts_pairs(base + SEC_E, row, khalf, wlo);
        }
    }
    {
        const int gtid = (mb * 2 + nb) * 256 + tid;
        #pragma unroll
        for (int it = 0; it < 4; it++) {
            const int pid = gtid + it * 65536;
            const int n = pid & (Hn - 1);
            const int k = (pid >> 8) * 2;
            uint32_t hi = pack_single(W1[(size_t)k * Hn + n], W1[(size_t)(k + 1) * Hn + n]);
            const int nbk = n >> 7, nloc = n & 127;
            const int c = k >> 5, s = (k >> 4) & 1, t = (k >> 1) & 7;
            const size_t base = (size_t)(nbk * (Dn / KC) + c) * IMG_B
                              + s * SBLK + nloc * 16 + (t & 3) * 4 + (t >> 2) * 2;
            *(uint32_t*)(g_w1p + base) = hi;
        }
    }
    {
        const int gtid = (mb * 2 + nb) * 256 + tid;
        #pragma unroll
        for (int it = 0; it < 16; it++) {
            const int pid = gtid + it * 65536;
            const int n = pid & (N2 - 1);
            const int k = (pid >> 13) * 2;
            uint32_t hi = pack_single(W2[(size_t)k * N2 + n], W2[(size_t)(k + 1) * N2 + n]);
            const int nbk = n >> 7, nloc = n & 127;
            const int c = k >> 5, s = (k >> 4) & 1, t = (k >> 1) & 7;
            const size_t base = (size_t)(nbk * (Hn / KC) + c) * IMG_B
                              + s * SBLK + nloc * 16 + (t & 3) * 4 + (t >> 2) * 2;
            *(uint32_t*)(g_w2p + base) = hi;
        }
    }

    // ===== Global barrier (all 256 CTAs resident: 148 SMs x 2) =====
    __syncthreads();
    if (tid == 0) {
        __threadfence();
        atomicAdd(&g_barIn, 1u);
        while (*(volatile unsigned*)&g_barIn < NCT) { }
        __threadfence();
        unsigned d = atomicAdd(&g_barOut, 1u) + 1;
        if (d == NCT) {
            *(volatile unsigned*)&g_barIn = 0;
            __threadfence();
            *(volatile unsigned*)&g_barOut = 0;
        }
    }
    __syncthreads();

    // ===== Phase B: cp.async pipelined mainloop (PIPE1 = 4, verbatim R16) =====
    float acc[2][8][4] = {};
    const int CH = Dn / KC;   // 64

    const __half* apg = g_xpack + (size_t)(mb * CH) * IMG_A + tid * 8;
    const __half* bpg = g_w1p   + (size_t)(nb * CH) * IMG_B + tid * 8;
    const uint32_t db0 = sbase + tid * 16;
    const uint32_t db1 = db0 + 2 * SEC_E * 2;

    #define G1_COPY_BUF(bufidx) {                                                 \
        const uint32_t bo = (bufidx) * STG1_B;                                     \
        _Pragma("unroll")                                                          \
        for (int j = 0; j < 4; j++)                                                \
            cp_async16(db0 + bo + j * 4096, apg + j * 2048);                       \
        _Pragma("unroll")                                                          \
        for (int j = 0; j < 2; j++)                                                \
            cp_async16(db1 + bo + j * 4096, bpg + j * 2048);                       \
        CP_COMMIT();                                                               \
        apg += IMG_A; bpg += IMG_B;                                                \
    }

    G1_COPY_BUF(0);
    G1_COPY_BUF(1);
    G1_COPY_BUF(2);

    int cb = 0;
    int pb = 3;
    #pragma unroll 4
    for (int c = 0; c < CH; c++) {
        if (c < CH - 1) { CP_WAIT(2); } else { CP_WAIT(0); }
        __syncthreads();
        if (c + 3 < CH) G1_COPY_BUF(pb);
        const __half* buf = sm + cb * STG1_E;
        compute_sub1(buf, 0, lane, wm, wn, acc);
        compute_sub1(buf, 1, lane, wm, wn, acc);
        cb = (cb + 1) & 3;
        pb = (pb + 1) & 3;
    }

    // ---- Epilogue: silu -> H packed hi-only image ----
    #pragma unroll
    for (int mt = 0; mt < 2; mt++) {
        const int r1 = wm * 32 + mt * 16 + (lane >> 2);
        #pragma unroll
        for (int nt = 0; nt < 8; nt++) {
            const int kcol = n0 + wn * 64 + nt * 8 + (lane & 3) * 2;
            const int cc = kcol >> 5, ss = (kcol >> 4) & 1, tt = (kcol >> 1) & 7;
            const size_t go = (size_t)(mb * (Hn / KC) + cc) * IMG_H
                            + ss * SBLK + (tt & 3) * 4 + (tt >> 2) * 2;
            float f0 = silu_f(acc[mt][nt][0]);
            float f1 = silu_f(acc[mt][nt][1]);
            float f2 = silu_f(acc[mt][nt][2]);
            float f3 = silu_f(acc[mt][nt][3]);
            *(uint32_t*)(g_hpack + go + r1 * 16)       = pack_single(f0, f1);
            *(uint32_t*)(g_hpack + go + (r1 + 8) * 16) = pack_single(f2, f3);
        }
    }
}

// ---------------- GEMM2: flat = H @ W2 + b2; fused conv + silu ----------------
#define XSP 36

__global__ __launch_bounds__(256, 2) void gemm2_mma_kernel(
    const float* __restrict__ X, const float* __restrict__ B2,
    float* __restrict__ OUT)
{
    extern __shared__ __align__(16) __half sm[];
    const int tid = threadIdx.x, lane = tid & 31, wid = tid >> 5;
    const int wm = wid & 3, wn = wid >> 2;
    const int m0 = blockIdx.y * 128, n0 = blockIdx.x * 128;
    const int nb = blockIdx.x, mb = blockIdx.y;
    const uint32_t sbase = s2u(sm);
    const int CH = Hn / KC;   // 8

    float acc[2][8][4] = {};

    #define G2_COPY(c) {                                                          \
        const __half* ap = g_hpack + (size_t)(mb * CH + (c)) * IMG_H;             \
        const __half* bp = g_w2p  + (size_t)(nb * CH + (c)) * IMG_B;              \
        const uint32_t db = sbase + ((c) % PIPE2) * STG2_B;                       \
        _Pragma("unroll")                                                         \
        for (int j = 0; j < 2; j++)                                               \
            cp_async16(db + (tid + j * 256) * 16, ap + (tid + j * 256) * 8);      \
        _Pragma("unroll")                                                         \
        for (int j = 0; j < 2; j++)                                               \
            cp_async16(db + SEC_E * 2 + (tid + j * 256) * 16,                     \
                       bp + (tid + j * 256) * 8);                                 \
        CP_COMMIT();                                                              \
    }

    G2_COPY(0);
    G2_COPY(1);
    G2_COPY(2);
    G2_COPY(3);
    G2_COPY(4);

    #pragma unroll
    for (int c = 0; c < CH; c++) {
        if (c < CH - 1) { CP_WAIT(4); } else { CP_WAIT(0); }
        __syncthreads();
        if (c + 5 < CH) G2_COPY(c + 5);
        const __half* buf = sm + (c % PIPE2) * STG2_E;
        compute_sub2(buf, 0, lane, wm, wn, acc);
        compute_sub2(buf, 1, lane, wm, wn, acc);
    }
    __syncthreads();   // smem about to be reused by the epilogue tiles

    // ---- Epilogue (structure verbatim R9-R16): X window / bias / OUT ----
    float* fs = (float*)sm;
    float* xs = fs;
    float* os = fs + 131 * XSP;
    float* bs = os + 128 * XSP;
    const int d0 = n0 >> 2;
    const int brow = (m0 / Tn) * Tn;

    for (int i = tid; i < 131 * 8; i += 256) {
        const int rw = i >> 3, c4 = (i & 7) * 4;
        const int gr = m0 - 3 + rw;
        float4 v = make_float4(0.f, 0.f, 0.f, 0.f);
        if (gr >= brow) v = *(const float4*)(X + (size_t)gr * Dn + d0 + c4);
        *(float4*)(xs + rw * XSP + c4) = v;
    }
    if (tid < 128) bs[tid] = B2[n0 + tid];
    __syncthreads();

    const int q = lane & 3;
    #pragma unroll
    for (int mt = 0; mt < 2; mt++) {
        const int rb = wm * 32 + mt * 16 + (lane >> 2);
        #pragma unroll
        for (int nt = 0; nt < 8; nt++) {
            const int colb = wn * 64 + nt * 8;
            const int col0 = colb + q * 2;
            const float bb0 = bs[col0], bb1 = bs[col0 + 1];
            float c0 = acc[mt][nt][0] + bb0;
            float c1 = acc[mt][nt][1] + bb1;
            float c2 = acc[mt][nt][2] + bb0;
            float c3 = acc[mt][nt][3] + bb1;
            float o0 = __shfl_xor_sync(0xffffffffu, c0, 1);
            float o1 = __shfl_xor_sync(0xffffffffu, c1, 1);
            float o2 = __shfl_xor_sync(0xffffffffu, c2, 1);
            float o3 = __shfl_xor_sync(0xffffffffu, c3, 1);

            float k0, k1, k2, k3;
            int rloc;
            if ((q & 1) == 0) { rloc = rb;     k0 = c0; k1 = c1; k2 = o0; k3 = o1; }
            else              { rloc = rb + 8; k0 = o2; k1 = o3; k2 = c2; k3 = c3; }
            const int dloc = (colb >> 2) + (q >> 1);

            const float* xp = xs + rloc * XSP + dloc;
            float o = k0 * xp[0] + k1 * xp[XSP] + k2 * xp[2 * XSP] + k3 * xp[3 * XSP];
            os[rloc * XSP + dloc] = silu_f(o);
        }
    }
    __syncthreads();

    for (int i = tid; i < 128 * 8; i += 256) {
        const int rw = i >> 3, c4 = (i & 7) * 4;
        *(float4*)(OUT + (size_t)(m0 + rw) * Dn + d0 + c4) = *(float4*)(os + rw * XSP + c4);
    }
}

// ---------------- launch ----------------
extern "C" void kernel_launch(void* const* d_in, const int* in_sizes, int n_in,
                              void* d_out, int out_size) {
    const float* x  = (const float*)d_in[0];   // [4,4096,2048]
    const float* w1 = (const float*)d_in[1];   // [2048,256]
    const float* w2 = (const float*)d_in[2];   // [256,8192]
    const float* b2 = (const float*)d_in[3];   // [8192]
    float* out = (float*)d_out;

    cudaFuncSetAttribute(gemm1_mma_kernel,
                         cudaFuncAttributeMaxDynamicSharedMemorySize, G1_SMEM);
    cudaFuncSetAttribute(gemm2_mma_kernel,
                         cudaFuncAttributeMaxDynamicSharedMemorySize, G2_SMEM);

    gemm1_mma_kernel<<<dim3(Hn / 128, Mn / 128), 256, G1_SMEM>>>(x, w1, w2);
    gemm2_mma_kernel<<<dim3(N2 / 128, Mn / 128), 256, G2_SMEM>>>(x, b2, out);
}